// round 14
// baseline (speedup 1.0000x reference)
#include <cuda_runtime.h>
#include <cuda_fp16.h>
#include <cstdint>

// ---------------------------------------------------------------------------
// Problem constants
// ---------------------------------------------------------------------------
#define MROWS 11520      // b*n = 2*5760
#define DIM   512        // d
#define HD    1960       // hidden
#define KK    7
#define PP    3
#define HH    60
#define WW    108
#define LH    20
#define LW    36
#define NB2   16
#define NCCH  40
#define PH    66
#define PW    114

// Scratch (device globals — no allocation allowed)
__device__ float  g_ht[HD * MROWS];           // h^T = (x@W1+b1)^T  [ch][tok]
__device__ float  g_F[NB2 * NCCH * PH * PW];  // folded padded image
__device__ __half g_xh[MROWS * DIM];          // x in fp16
__device__ __half g_Ah[MROWS * HD];           // relu(unfold(F/norm)) in fp16
__device__ __half g_W1h[HD * DIM];            // fp16 W1^T [N=1960][K=512]
__device__ __half g_W2h[DIM * HD];            // fp16 W2^T [N=512][K=1960]

// ---------------------------------------------------------------------------
// helpers
// ---------------------------------------------------------------------------
__device__ __forceinline__ uint32_t smem_u32(const void* p) {
    uint32_t a;
    asm("{ .reg .u64 t; cvta.to.shared.u64 t, %1; cvt.u32.u64 %0, t; }"
        : "=r"(a) : "l"(p));
    return a;
}

#define LDSM_X4(r0, r1, r2, r3, a)                                            \
    asm volatile("ldmatrix.sync.aligned.m8n8.x4.shared.b16 {%0,%1,%2,%3}, [%4];" \
                 : "=r"(r0), "=r"(r1), "=r"(r2), "=r"(r3) : "r"(a))

__device__ __forceinline__ void mma_f16(float* c, const uint32_t* a,
                                        uint32_t b0, uint32_t b1) {
    asm volatile(
        "mma.sync.aligned.m16n8k16.row.col.f32.f16.f16.f32 "
        "{%0,%1,%2,%3}, {%4,%5,%6,%7}, {%8,%9}, {%0,%1,%2,%3};"
        : "+f"(c[0]), "+f"(c[1]), "+f"(c[2]), "+f"(c[3])
        : "r"(a[0]), "r"(a[1]), "r"(a[2]), "r"(a[3]), "r"(b0), "r"(b1));
}

#define CP_ASYNC_CG(dst, src, sz)                                             \
    asm volatile("cp.async.cg.shared.global [%0], [%1], 16, %2;"              \
                 :: "r"(dst), "l"(src), "r"(sz) : "memory")
#define CP_COMMIT() asm volatile("cp.async.commit_group;" ::: "memory")
#define CP_WAIT1()  asm volatile("cp.async.wait_group 1;" ::: "memory")

// ---------------------------------------------------------------------------
// fp16 MMA GEMM:  C = A[M,K] @ B[N,K]^T + bias[N]
//   TRANSC=false: C[M,N] row-major    TRANSC=true: C^T[N,M] (coalesced rows)
// CTA tile 128x128, BK=64, 256 threads (8 warps, 2(m) x 4(n), 64x32 warp tile)
// 3-stage cp.async pipeline, one __syncthreads per 64-K iteration.
// SMEM row stride 144 B => conflict-free ldmatrix.
// ---------------------------------------------------------------------------
#define BSTRIDE 144                      // bytes per row (64 halves + pad)
#define TILE_B  (128 * BSTRIDE)          // 18432 B per matrix tile
#define OFF_A   0
#define OFF_B   (TILE_B)
#define STAGE_B (2 * TILE_B)             // 36864 B per stage
#define NSTAGE  3
#define SMEM_TOTAL (NSTAGE * STAGE_B)    // 110592 B (>= epilogue 68096 B)

template <bool TRANSC>
__global__ __launch_bounds__(256, 2)
void f16_gemm(const __half* __restrict__ A, const __half* __restrict__ B,
              const float* __restrict__ bias, float* __restrict__ C,
              int M, int N, int K)
{
    extern __shared__ char smem[];
    const uint32_t sbase = smem_u32(smem);

    const int tid  = threadIdx.x;
    const int wid  = tid >> 5;
    const int lane = tid & 31;
    const int warp_m = (wid & 1) * 64;
    const int warp_n = (wid >> 1) * 32;

    const int bm = blockIdx.y * 128;
    const int bn = blockIdx.x * 128;
    const int nIter = (K + 63) / 64;

    // loader mapping: each thread: row = tid>>1, 4 chunks of 16B (64B run)
    const int ldRow  = tid >> 1;
    const int cBase  = (tid & 1) * 4;

    auto issue = [&](int it) {
        const int k0 = it * 64;
        const uint32_t stg = sbase + (uint32_t)(it % NSTAGE) * STAGE_B;
        const int ng = bn + ldRow;
        const int srow = (ng < N) ? ng : 0;
        const long long arow = (long long)(bm + ldRow) * K;
        const long long brow = (long long)srow * K;
#pragma unroll
        for (int j = 0; j < 4; j++) {
            int c = cBase + j;
            int kpos = k0 + c * 8;
            int rem = K - kpos;
            uint32_t bytes = rem >= 8 ? 16u : (rem > 0 ? (uint32_t)(rem * 2) : 0u);
            int ksafe = (kpos < K) ? kpos : 0;
            uint32_t doff = (uint32_t)(ldRow * BSTRIDE + c * 16);
            CP_ASYNC_CG(stg + OFF_A + doff, A + arow + ksafe, bytes);
            uint32_t bbytes = (ng < N) ? bytes : 0u;
            CP_ASYNC_CG(stg + OFF_B + doff, B + brow + ksafe, bbytes);
        }
        CP_COMMIT();
    };

    float acc[4][4][4];
#pragma unroll
    for (int i = 0; i < 4; i++)
#pragma unroll
        for (int j = 0; j < 4; j++)
#pragma unroll
            for (int e = 0; e < 4; e++) acc[i][j][e] = 0.0f;

    issue(0);
    issue(1);
    CP_WAIT1();                 // stage 0 ready
    __syncthreads();

    const int rowSel = lane & 15;
    const uint32_t kHalf = ((uint32_t)(lane >> 4)) << 4;   // 0 or 16 B

    for (int it = 0; it < nIter; it++) {
        const uint32_t stg = sbase + (uint32_t)(it % NSTAGE) * STAGE_B;

#pragma unroll
        for (int ks = 0; ks < 4; ks++) {
            const uint32_t kb = (uint32_t)(ks * 32) + kHalf;
            uint32_t ah[4][4], bh[2][4];
#pragma unroll
            for (int mt = 0; mt < 4; mt++) {
                uint32_t ra = (uint32_t)((warp_m + mt * 16 + rowSel) * BSTRIDE) + kb;
                LDSM_X4(ah[mt][0], ah[mt][1], ah[mt][2], ah[mt][3], stg + OFF_A + ra);
            }
#pragma unroll
            for (int ng = 0; ng < 2; ng++) {
                uint32_t rb = (uint32_t)((warp_n + ng * 16 + rowSel) * BSTRIDE) + kb;
                LDSM_X4(bh[ng][0], bh[ng][1], bh[ng][2], bh[ng][3], stg + OFF_B + rb);
            }
#pragma unroll
            for (int mt = 0; mt < 4; mt++)
#pragma unroll
                for (int ng = 0; ng < 2; ng++)
#pragma unroll
                    for (int hf = 0; hf < 2; hf++)
                        mma_f16(acc[mt][ng * 2 + hf], ah[mt],
                                bh[ng][hf], bh[ng][hf + 2]);
        }

        // prefetch stage it+2 (overwrites stage (it-1)%3 — safe post-sync)
        if (it + 2 < nIter) issue(it + 2);
        else                CP_COMMIT();
        CP_WAIT1();            // stage it+1 ready
        __syncthreads();
    }

    // ---- epilogue through smem ----
    constexpr int EPS = TRANSC ? 133 : 132;   // 133: odd => scalar path only
    float* sf = (float*)smem;
    {
        const int r0 = lane >> 2;
        const int c0 = (lane & 3) * 2;
#pragma unroll
        for (int mt = 0; mt < 4; mt++)
#pragma unroll
            for (int n8 = 0; n8 < 4; n8++) {
                int row = warp_m + mt * 16 + r0;
                int col = warp_n + n8 * 8 + c0;
                float* c = acc[mt][n8];
                if (TRANSC) {
                    // scalar stores: row*133+col may be odd (float2 would fault)
                    sf[row * EPS + col]           = c[0];
                    sf[row * EPS + col + 1]       = c[1];
                    sf[(row + 8) * EPS + col]     = c[2];
                    sf[(row + 8) * EPS + col + 1] = c[3];
                } else {
                    *(float2*)&sf[row * EPS + col]       = make_float2(c[0], c[1]);
                    *(float2*)&sf[(row + 8) * EPS + col] = make_float2(c[2], c[3]);
                }
            }
    }
    __syncthreads();

    if (TRANSC) {
        // C^T[N][M]: lanes -> consecutive token rows; scalar stores are
        // 128B-coalesced per warp; smem stride 133 (mod 32 = 5) conflict-free.
#pragma unroll
        for (int t = 0; t < 64; t++) {
            int idx = tid + t * 256;       // 0..16383
            int col = idx >> 7;            // output channel 0..127
            int row = idx & 127;           // token row 0..127
            if (bn + col < N)
                C[(long long)(bn + col) * M + bm + row] =
                    sf[row * EPS + col] + bias[bn + col];
        }
    } else if (bn + 128 <= N) {
#pragma unroll
        for (int t = 0; t < 16; t++) {
            int idx = tid + t * 256;
            int row = idx >> 5;
            int c4 = (idx & 31) * 4;
            float4 bv = *(const float4*)(bias + bn + c4);
            float4 o;
            o.x = sf[row * EPS + c4 + 0] + bv.x;
            o.y = sf[row * EPS + c4 + 1] + bv.y;
            o.z = sf[row * EPS + c4 + 2] + bv.z;
            o.w = sf[row * EPS + c4 + 3] + bv.w;
            *(float4*)(C + (long long)(bm + row) * N + bn + c4) = o;
        }
    } else {
        for (int idx = tid; idx < 128 * 128; idx += 256) {
            int row = idx >> 7;
            int col = idx & 127;
            if (bn + col < N)
                C[(long long)(bm + row) * N + bn + col] =
                    sf[row * EPS + col] + bias[bn + col];
        }
    }
}

// ---------------------------------------------------------------------------
// Transpose + fp16 convert: in[R][C] fp32 -> out[C][R] fp16
// ---------------------------------------------------------------------------
__global__ void transpose_cvt_kernel(const float* __restrict__ in,
                                     __half* __restrict__ out, int R, int C) {
    __shared__ float t[32][33];
    int bx = blockIdx.x * 32, by = blockIdx.y * 32;
    int x = bx + threadIdx.x;
#pragma unroll
    for (int j = threadIdx.y; j < 32; j += 8) {
        int r = by + j;
        t[j][threadIdx.x] = (r < R && x < C) ? in[(long long)r * C + x] : 0.0f;
    }
    __syncthreads();
    int xo = by + threadIdx.x;
#pragma unroll
    for (int j = threadIdx.y; j < 32; j += 8) {
        int co = bx + j;
        if (co < C && xo < R)
            out[(long long)co * R + xo] = __float2half_rn(t[threadIdx.x][j]);
    }
}

// ---------------------------------------------------------------------------
// fp32 -> fp16 convert (float4 granularity)
// ---------------------------------------------------------------------------
__global__ void cvt_f16_kernel(const float* __restrict__ in,
                               __half* __restrict__ out, int n4) {
    int i = blockIdx.x * blockDim.x + threadIdx.x;
    if (i >= n4) return;
    float4 v = ((const float4*)in)[i];
    ((__half2*)out)[i * 2]     = __floats2half2_rn(v.x, v.y);
    ((__half2*)out)[i * 2 + 1] = __floats2half2_rn(v.z, v.w);
}

// ---------------------------------------------------------------------------
// Fold (gather, no atomics), reading h^T[ch][tok]: same-(ki,kj) lanes hit
// consecutive tokens -> coalesced sectors instead of 1 sector per lane.
// ---------------------------------------------------------------------------
__global__ void fold_kernel() {
    int idx = blockIdx.x * blockDim.x + threadIdx.x;
    const int total = NB2 * NCCH * PH * PW;
    if (idx >= total) return;

    int pc = idx % PW;
    int t = idx / PW;
    int pr = t % PH; t /= PH;
    int cch = t % NCCH;
    int b2 = t / NCCH;

    float s = 0.0f;
    int ki0 = pr % 3, kj0 = pc % 3;
#pragma unroll
    for (int ki = ki0; ki < KK; ki += 3) {
        int lh3 = pr - ki;
        if (lh3 < 0 || lh3 > 3 * (LH - 1)) continue;
        int lh = lh3 / 3;
#pragma unroll
        for (int kj = kj0; kj < KK; kj += 3) {
            int lw3 = pc - kj;
            if (lw3 < 0 || lw3 > 3 * (LW - 1)) continue;
            int lw = lw3 / 3;
            int ch = (cch * KK + ki) * KK + kj;
            int tok = (b2 * LH + lh) * LW + lw;
            s += g_ht[(long long)ch * MROWS + tok];
        }
    }
    g_F[idx] = s;
}

__device__ __forceinline__ float inv_count(int p, int lmax3) {
    int c = 0;
#pragma unroll
    for (int k = p % 3; k < KK; k += 3) {
        int l3 = p - k;
        if (l3 >= 0 && l3 <= lmax3) c++;
    }
    return 1.0f / (float)c;
}

// ---------------------------------------------------------------------------
// Unfold + normalize + ReLU -> fp16 A (4 channels / thread)
// ---------------------------------------------------------------------------
__global__ void unfold_relu_kernel() {
    int idx = blockIdx.x * blockDim.x + threadIdx.x;
    const int total = MROWS * (HD / 4);
    if (idx >= total) return;

    int c4 = (idx % (HD / 4)) * 4;
    int m = idx / (HD / 4);
    int lw = m % LW;
    int t = m / LW;
    int lh = t % LH;
    int b2 = t / LH;

    const float* Fb = g_F + (long long)b2 * NCCH * PH * PW;
    float o[4];
#pragma unroll
    for (int e = 0; e < 4; e++) {
        int ch = c4 + e;
        int kj = ch % KK;
        int t2 = ch / KK;
        int ki = t2 % KK;
        int cch = t2 / KK;
        int pr = ki + 3 * lh;
        int pc = kj + 3 * lw;
        float v = 0.0f;
        if (pr >= PP && pr < PP + HH && pc >= PP && pc < PP + WW) {
            float f = Fb[((long long)cch * PH + pr) * PW + pc];
            f = fmaxf(f, 0.0f);
            v = f * inv_count(pr, 3 * (LH - 1)) * inv_count(pc, 3 * (LW - 1));
        }
        o[e] = v;
    }
    __half2 p0 = __floats2half2_rn(o[0], o[1]);
    __half2 p1 = __floats2half2_rn(o[2], o[3]);
    __half2* dst = (__half2*)(g_Ah + (long long)m * HD + c4);
    dst[0] = p0;
    dst[1] = p1;
}

// ---------------------------------------------------------------------------
extern "C" void kernel_launch(void* const* d_in, const int* in_sizes, int n_in,
                              void* d_out, int out_size) {
    const float* x  = (const float*)d_in[0];
    const float* W1 = (const float*)d_in[1];
    const float* b1 = (const float*)d_in[2];
    const float* W2 = (const float*)d_in[3];
    const float* b2 = (const float*)d_in[4];
    float* out = (float*)d_out;

    float* htP;
    __half *xhP, *AhP, *W1hP, *W2hP;
    cudaGetSymbolAddress((void**)&htP, g_ht);
    cudaGetSymbolAddress((void**)&xhP, g_xh);
    cudaGetSymbolAddress((void**)&AhP, g_Ah);
    cudaGetSymbolAddress((void**)&W1hP, g_W1h);
    cudaGetSymbolAddress((void**)&W2hP, g_W2h);

    cudaFuncSetAttribute(f16_gemm<true>,
                         cudaFuncAttributeMaxDynamicSharedMemorySize, SMEM_TOTAL);
    cudaFuncSetAttribute(f16_gemm<false>,
                         cudaFuncAttributeMaxDynamicSharedMemorySize, SMEM_TOTAL);

    // Pre-transpose + convert weights to fp16, [N][K] K-major
    {
        dim3 blk(32, 8);
        dim3 g1((HD + 31) / 32, (DIM + 31) / 32);
        transpose_cvt_kernel<<<g1, blk>>>(W1, W1hP, DIM, HD);
        dim3 g2((DIM + 31) / 32, (HD + 31) / 32);
        transpose_cvt_kernel<<<g2, blk>>>(W2, W2hP, HD, DIM);
    }

    // x -> fp16
    {
        int n4 = MROWS * DIM / 4;
        cvt_f16_kernel<<<(n4 + 255) / 256, 256>>>(x, xhP, n4);
    }

    // GEMM1: h^T = (x @ W1 + b1)^T   (M=11520, N=1960, K=512), transposed out
    {
        dim3 grid((HD + 127) / 128, MROWS / 128);
        f16_gemm<true><<<grid, 256, SMEM_TOTAL>>>(xhP, W1hP, b1, htP,
                                                  MROWS, HD, DIM);
    }

    // Fold
    {
        int total = NB2 * NCCH * PH * PW;
        fold_kernel<<<(total + 255) / 256, 256>>>();
    }

    // Unfold + normalize + ReLU -> fp16
    {
        int total = MROWS * (HD / 4);
        unfold_relu_kernel<<<(total + 255) / 256, 256>>>();
    }

    // GEMM2: out = A @ W2 + b2  (M=11520, N=512, K=1960)
    {
        dim3 grid((DIM + 127) / 128, MROWS / 128);
        f16_gemm<false><<<grid, 256, SMEM_TOTAL>>>(AhP, W2hP, b2, out,
                                                   MROWS, DIM, HD);
    }
}

// round 15
// speedup vs baseline: 1.1714x; 1.1714x over previous
#include <cuda_runtime.h>
#include <cuda_fp16.h>
#include <cstdint>

// ---------------------------------------------------------------------------
// Problem constants
// ---------------------------------------------------------------------------
#define MROWS 11520      // b*n = 2*5760
#define DIM   512        // d
#define HD    1960       // hidden
#define KK    7
#define PP    3
#define HH    60
#define WW    108
#define LH    20
#define LW    36
#define NB2   16
#define NCCH  40
#define PH    66
#define PW    114

// Scratch (device globals — no allocation allowed)
__device__ float  g_ht[HD * MROWS];           // h^T = (x@W1+b1)^T  [ch][tok]
__device__ float  g_F[NB2 * NCCH * PH * PW];  // folded padded image
__device__ __half g_xh[MROWS * DIM];          // x in fp16
__device__ __half g_Ah[MROWS * HD];           // relu(unfold(F/norm)) in fp16
__device__ __half g_W1h[HD * DIM];            // fp16 W1^T [N=1960][K=512]
__device__ __half g_W2h[DIM * HD];            // fp16 W2^T [N=512][K=1960]

// ---------------------------------------------------------------------------
// helpers
// ---------------------------------------------------------------------------
__device__ __forceinline__ uint32_t smem_u32(const void* p) {
    uint32_t a;
    asm("{ .reg .u64 t; cvta.to.shared.u64 t, %1; cvt.u32.u64 %0, t; }"
        : "=r"(a) : "l"(p));
    return a;
}

#define LDSM_X4(r0, r1, r2, r3, a)                                            \
    asm volatile("ldmatrix.sync.aligned.m8n8.x4.shared.b16 {%0,%1,%2,%3}, [%4];" \
                 : "=r"(r0), "=r"(r1), "=r"(r2), "=r"(r3) : "r"(a))

__device__ __forceinline__ void mma_f16(float* c, const uint32_t* a,
                                        uint32_t b0, uint32_t b1) {
    asm volatile(
        "mma.sync.aligned.m16n8k16.row.col.f32.f16.f16.f32 "
        "{%0,%1,%2,%3}, {%4,%5,%6,%7}, {%8,%9}, {%0,%1,%2,%3};"
        : "+f"(c[0]), "+f"(c[1]), "+f"(c[2]), "+f"(c[3])
        : "r"(a[0]), "r"(a[1]), "r"(a[2]), "r"(a[3]), "r"(b0), "r"(b1));
}

#define CP_ASYNC_CG(dst, src, sz)                                             \
    asm volatile("cp.async.cg.shared.global [%0], [%1], 16, %2;"              \
                 :: "r"(dst), "l"(src), "r"(sz) : "memory")
#define CP_COMMIT() asm volatile("cp.async.commit_group;" ::: "memory")
#define CP_WAIT1()  asm volatile("cp.async.wait_group 1;" ::: "memory")

// ---------------------------------------------------------------------------
// fp16 MMA GEMM (R12-proven shape):  C = A[M,K] @ B[N,K]^T + bias[N]
//   TRANSC=false: C[M,N] row-major    TRANSC=true: C^T[N,M] (coalesced rows)
// CTA tile 128x128, BK=32, 256 threads (8 warps, 2(m) x 4(n), 64x32 warp tile)
// 3-stage cp.async pipeline, one __syncthreads per iter.
// SMEM row stride 80 B => conflict-free ldmatrix.
// ---------------------------------------------------------------------------
#define BSTRIDE 80                       // bytes per row (32 halves + pad)
#define TILE_B  (128 * BSTRIDE)          // 10240 B per matrix tile
#define OFF_A   0
#define OFF_B   (TILE_B)
#define STAGE_B (2 * TILE_B)             // 20480 B per stage
#define NSTAGE  3                        // 61440 B total stages
#define SMEM_TOTAL 67584                 // epilogue 128*132*4 dominates

template <bool TRANSC>
__global__ __launch_bounds__(256, 2)
void f16_gemm(const __half* __restrict__ A, const __half* __restrict__ B,
              const float* __restrict__ bias, float* __restrict__ C,
              int M, int N, int K)
{
    extern __shared__ char smem[];
    const uint32_t sbase = smem_u32(smem);

    const int tid  = threadIdx.x;
    const int wid  = tid >> 5;
    const int lane = tid & 31;
    const int warp_m = (wid & 1) * 64;
    const int warp_n = (wid >> 1) * 32;

    const int bm = blockIdx.y * 128;
    const int bn = blockIdx.x * 128;
    const int nIter = (K + 31) / 32;

    // per-thread chunk coords (16B chunks): 512 chunks / 256 thr = 2 each
    const int ch0row = tid >> 2;              // rows 0..63
    const int ch0c   = tid & 3;
    const int ch1row = ch0row + 64;           // rows 64..127

    auto issue = [&](int it) {
        const int k0 = it * 32;
        const uint32_t stg = sbase + (uint32_t)(it % NSTAGE) * STAGE_B;
        const int kpos = k0 + ch0c * 8;
        const int rem = K - kpos;
        const uint32_t bytes = rem >= 8 ? 16u : (rem > 0 ? (uint32_t)(rem * 2) : 0u);
        const int ksafe = (kpos < K) ? kpos : 0;
#pragma unroll
        for (int j = 0; j < 2; j++) {
            int row = j ? ch1row : ch0row;
            uint32_t doff = (uint32_t)(row * BSTRIDE + ch0c * 16);
            const __half* asrc = A + (long long)(bm + row) * K + ksafe;
            CP_ASYNC_CG(stg + OFF_A + doff, asrc, bytes);

            int ng = bn + row;
            int srow = (ng < N) ? ng : (N - 1);
            uint32_t bbytes = (ng < N) ? bytes : 0u;
            const __half* bsrc = B + (long long)srow * K + ksafe;
            CP_ASYNC_CG(stg + OFF_B + doff, bsrc, bbytes);
        }
        CP_COMMIT();
    };

    float acc[4][4][4];
#pragma unroll
    for (int i = 0; i < 4; i++)
#pragma unroll
        for (int j = 0; j < 4; j++)
#pragma unroll
            for (int e = 0; e < 4; e++) acc[i][j][e] = 0.0f;

    issue(0);
    issue(1);
    CP_WAIT1();                 // stage 0 ready
    __syncthreads();

    const int rowSel = lane & 15;
    const uint32_t kHalf = ((uint32_t)(lane >> 4)) << 4;   // 0 or 16 B

    for (int it = 0; it < nIter; it++) {
        const uint32_t stg = sbase + (uint32_t)(it % NSTAGE) * STAGE_B;

#pragma unroll
        for (int ks = 0; ks < 2; ks++) {
            const uint32_t kb = (uint32_t)(ks * 32) + kHalf;
            uint32_t ah[4][4], bh[2][4];
#pragma unroll
            for (int mt = 0; mt < 4; mt++) {
                uint32_t ra = (uint32_t)((warp_m + mt * 16 + rowSel) * BSTRIDE) + kb;
                LDSM_X4(ah[mt][0], ah[mt][1], ah[mt][2], ah[mt][3], stg + OFF_A + ra);
            }
#pragma unroll
            for (int ng = 0; ng < 2; ng++) {
                uint32_t rb = (uint32_t)((warp_n + ng * 16 + rowSel) * BSTRIDE) + kb;
                LDSM_X4(bh[ng][0], bh[ng][1], bh[ng][2], bh[ng][3], stg + OFF_B + rb);
            }
#pragma unroll
            for (int mt = 0; mt < 4; mt++)
#pragma unroll
                for (int ng = 0; ng < 2; ng++)
#pragma unroll
                    for (int hf = 0; hf < 2; hf++)
                        mma_f16(acc[mt][ng * 2 + hf], ah[mt],
                                bh[ng][hf], bh[ng][hf + 2]);
        }

        // prefetch stage it+2 (overwrites stage (it-1)%3 — safe post-sync)
        if (it + 2 < nIter) issue(it + 2);
        else                CP_COMMIT();
        CP_WAIT1();            // stage it+1 ready
        __syncthreads();
    }

    // ---- epilogue through smem ----
    float* sf = (float*)smem;                 // 128 x 132 floats = 67584 B
    {
        const int r0 = lane >> 2;
        const int c0 = (lane & 3) * 2;
#pragma unroll
        for (int mt = 0; mt < 4; mt++)
#pragma unroll
            for (int n8 = 0; n8 < 4; n8++) {
                int row = warp_m + mt * 16 + r0;
                int col = warp_n + n8 * 8 + c0;
                float* c = acc[mt][n8];
                if (TRANSC) {
                    // stage transposed: sf[col][row], scalar stores
                    sf[col * 132 + row]           = c[0];
                    sf[(col + 1) * 132 + row]     = c[1];
                    sf[col * 132 + row + 8]       = c[2];
                    sf[(col + 1) * 132 + row + 8] = c[3];
                } else {
                    *(float2*)&sf[row * 132 + col]       = make_float2(c[0], c[1]);
                    *(float2*)&sf[(row + 8) * 132 + col] = make_float2(c[2], c[3]);
                }
            }
    }
    __syncthreads();

    if (TRANSC) {
        // C^T[N][M]: float4 along tokens; 132 ≡ 0 (mod 4) so sf reads aligned
#pragma unroll
        for (int t = 0; t < 16; t++) {
            int idx = tid + t * 256;       // 0..4095
            int col = idx >> 5;            // output channel 0..127
            int r4  = (idx & 31) * 4;      // token row group 0..124
            if (bn + col < N) {
                float b = bias[bn + col];
                float4 v = *(const float4*)&sf[col * 132 + r4];
                v.x += b; v.y += b; v.z += b; v.w += b;
                *(float4*)(C + (long long)(bn + col) * M + bm + r4) = v;
            }
        }
    } else if (bn + 128 <= N) {
#pragma unroll
        for (int t = 0; t < 16; t++) {
            int idx = tid + t * 256;
            int row = idx >> 5;
            int c4 = (idx & 31) * 4;
            float4 bv = *(const float4*)(bias + bn + c4);
            float4 o;
            o.x = sf[row * 132 + c4 + 0] + bv.x;
            o.y = sf[row * 132 + c4 + 1] + bv.y;
            o.z = sf[row * 132 + c4 + 2] + bv.z;
            o.w = sf[row * 132 + c4 + 3] + bv.w;
            *(float4*)(C + (long long)(bm + row) * N + bn + c4) = o;
        }
    } else {
        for (int idx = tid; idx < 128 * 128; idx += 256) {
            int row = idx >> 7;
            int col = idx & 127;
            if (bn + col < N)
                C[(long long)(bm + row) * N + bn + col] =
                    sf[row * 132 + col] + bias[bn + col];
        }
    }
}

// ---------------------------------------------------------------------------
// Transpose + fp16 convert: in[R][C] fp32 -> out[C][R] fp16
// ---------------------------------------------------------------------------
__global__ void transpose_cvt_kernel(const float* __restrict__ in,
                                     __half* __restrict__ out, int R, int C) {
    __shared__ float t[32][33];
    int bx = blockIdx.x * 32, by = blockIdx.y * 32;
    int x = bx + threadIdx.x;
#pragma unroll
    for (int j = threadIdx.y; j < 32; j += 8) {
        int r = by + j;
        t[j][threadIdx.x] = (r < R && x < C) ? in[(long long)r * C + x] : 0.0f;
    }
    __syncthreads();
    int xo = by + threadIdx.x;
#pragma unroll
    for (int j = threadIdx.y; j < 32; j += 8) {
        int co = bx + j;
        if (co < C && xo < R)
            out[(long long)co * R + xo] = __float2half_rn(t[threadIdx.x][j]);
    }
}

// ---------------------------------------------------------------------------
// fp32 -> fp16 convert (float4 granularity)
// ---------------------------------------------------------------------------
__global__ void cvt_f16_kernel(const float* __restrict__ in,
                               __half* __restrict__ out, int n4) {
    int i = blockIdx.x * blockDim.x + threadIdx.x;
    if (i >= n4) return;
    float4 v = ((const float4*)in)[i];
    ((__half2*)out)[i * 2]     = __floats2half2_rn(v.x, v.y);
    ((__half2*)out)[i * 2 + 1] = __floats2half2_rn(v.z, v.w);
}

// ---------------------------------------------------------------------------
// Fold (gather, no atomics), reading h^T[ch][tok]: warp lanes (consecutive pc)
// hit consecutive tokens -> coalesced sectors.
// ---------------------------------------------------------------------------
__global__ void fold_kernel() {
    int idx = blockIdx.x * blockDim.x + threadIdx.x;
    const int total = NB2 * NCCH * PH * PW;
    if (idx >= total) return;

    int pc = idx % PW;
    int t = idx / PW;
    int pr = t % PH; t /= PH;
    int cch = t % NCCH;
    int b2 = t / NCCH;

    float s = 0.0f;
    int ki0 = pr % 3, kj0 = pc % 3;
#pragma unroll
    for (int ki = ki0; ki < KK; ki += 3) {
        int lh3 = pr - ki;
        if (lh3 < 0 || lh3 > 3 * (LH - 1)) continue;
        int lh = lh3 / 3;
#pragma unroll
        for (int kj = kj0; kj < KK; kj += 3) {
            int lw3 = pc - kj;
            if (lw3 < 0 || lw3 > 3 * (LW - 1)) continue;
            int lw = lw3 / 3;
            int ch = (cch * KK + ki) * KK + kj;
            int tok = (b2 * LH + lh) * LW + lw;
            s += g_ht[(long long)ch * MROWS + tok];
        }
    }
    g_F[idx] = s;
}

__device__ __forceinline__ float inv_count(int p, int lmax3) {
    int c = 0;
#pragma unroll
    for (int k = p % 3; k < KK; k += 3) {
        int l3 = p - k;
        if (l3 >= 0 && l3 <= lmax3) c++;
    }
    return 1.0f / (float)c;
}

// ---------------------------------------------------------------------------
// Unfold + normalize + ReLU -> fp16 A (4 channels / thread)
// ---------------------------------------------------------------------------
__global__ void unfold_relu_kernel() {
    int idx = blockIdx.x * blockDim.x + threadIdx.x;
    const int total = MROWS * (HD / 4);
    if (idx >= total) return;

    int c4 = (idx % (HD / 4)) * 4;
    int m = idx / (HD / 4);
    int lw = m % LW;
    int t = m / LW;
    int lh = t % LH;
    int b2 = t / LH;

    const float* Fb = g_F + (long long)b2 * NCCH * PH * PW;
    float o[4];
#pragma unroll
    for (int e = 0; e < 4; e++) {
        int ch = c4 + e;
        int kj = ch % KK;
        int t2 = ch / KK;
        int ki = t2 % KK;
        int cch = t2 / KK;
        int pr = ki + 3 * lh;
        int pc = kj + 3 * lw;
        float v = 0.0f;
        if (pr >= PP && pr < PP + HH && pc >= PP && pc < PP + WW) {
            float f = Fb[((long long)cch * PH + pr) * PW + pc];
            f = fmaxf(f, 0.0f);
            v = f * inv_count(pr, 3 * (LH - 1)) * inv_count(pc, 3 * (LW - 1));
        }
        o[e] = v;
    }
    __half2 p0 = __floats2half2_rn(o[0], o[1]);
    __half2 p1 = __floats2half2_rn(o[2], o[3]);
    __half2* dst = (__half2*)(g_Ah + (long long)m * HD + c4);
    dst[0] = p0;
    dst[1] = p1;
}

// ---------------------------------------------------------------------------
extern "C" void kernel_launch(void* const* d_in, const int* in_sizes, int n_in,
                              void* d_out, int out_size) {
    const float* x  = (const float*)d_in[0];
    const float* W1 = (const float*)d_in[1];
    const float* b1 = (const float*)d_in[2];
    const float* W2 = (const float*)d_in[3];
    const float* b2 = (const float*)d_in[4];
    float* out = (float*)d_out;

    float* htP;
    __half *xhP, *AhP, *W1hP, *W2hP;
    cudaGetSymbolAddress((void**)&htP, g_ht);
    cudaGetSymbolAddress((void**)&xhP, g_xh);
    cudaGetSymbolAddress((void**)&AhP, g_Ah);
    cudaGetSymbolAddress((void**)&W1hP, g_W1h);
    cudaGetSymbolAddress((void**)&W2hP, g_W2h);

    cudaFuncSetAttribute(f16_gemm<true>,
                         cudaFuncAttributeMaxDynamicSharedMemorySize, SMEM_TOTAL);
    cudaFuncSetAttribute(f16_gemm<false>,
                         cudaFuncAttributeMaxDynamicSharedMemorySize, SMEM_TOTAL);

    // Pre-transpose + convert weights to fp16, [N][K] K-major
    {
        dim3 blk(32, 8);
        dim3 g1((HD + 31) / 32, (DIM + 31) / 32);
        transpose_cvt_kernel<<<g1, blk>>>(W1, W1hP, DIM, HD);
        dim3 g2((DIM + 31) / 32, (HD + 31) / 32);
        transpose_cvt_kernel<<<g2, blk>>>(W2, W2hP, HD, DIM);
    }

    // x -> fp16
    {
        int n4 = MROWS * DIM / 4;
        cvt_f16_kernel<<<(n4 + 255) / 256, 256>>>(x, xhP, n4);
    }

    // GEMM1: h^T = (x @ W1 + b1)^T   (M=11520, N=1960, K=512), transposed out
    {
        dim3 grid((HD + 127) / 128, MROWS / 128);
        f16_gemm<true><<<grid, 256, SMEM_TOTAL>>>(xhP, W1hP, b1, htP,
                                                  MROWS, HD, DIM);
    }

    // Fold
    {
        int total = NB2 * NCCH * PH * PW;
        fold_kernel<<<(total + 255) / 256, 256>>>();
    }

    // Unfold + normalize + ReLU -> fp16
    {
        int total = MROWS * (HD / 4);
        unfold_relu_kernel<<<(total + 255) / 256, 256>>>();
    }

    // GEMM2: out = A @ W2 + b2  (M=11520, N=512, K=1960)
    {
        dim3 grid((DIM + 127) / 128, MROWS / 128);
        f16_gemm<false><<<grid, 256, SMEM_TOTAL>>>(AhP, W2hP, b2, out,
                                                   MROWS, DIM, HD);
    }
}

// round 17
// speedup vs baseline: 1.1916x; 1.0172x over previous
#include <cuda_runtime.h>
#include <cuda_fp16.h>
#include <cstdint>

// ---------------------------------------------------------------------------
// Problem constants
// ---------------------------------------------------------------------------
#define MROWS 11520      // b*n = 2*5760
#define DIM   512        // d
#define HD    1960       // hidden
#define KK    7
#define PP    3
#define HH    60
#define WW    108
#define LH    20
#define LW    36
#define NB2   16
#define NCCH  40
#define PH    66
#define PW    114
#define KSPLIT 992       // GEMM2 split point (16B-aligned; 31 iters each side)

// Scratch (device globals — no allocation allowed)
__device__ float  g_ht[HD * MROWS];           // h^T = (x@W1+b1)^T  [ch][tok]
__device__ float  g_F[NB2 * NCCH * PH * PW];  // folded padded image
__device__ __half g_xh[MROWS * DIM];          // x in fp16
__device__ __half g_Ah[MROWS * HD];           // relu(unfold(F/norm)) in fp16
__device__ __half g_W1h[HD * DIM];            // fp16 W1^T [N=1960][K=512]
__device__ __half g_W2h[DIM * HD];            // fp16 W2^T [N=512][K=1960]
__device__ float  g_P0[MROWS * DIM];          // GEMM2 split-K partial 0
__device__ float  g_P1[MROWS * DIM];          // GEMM2 split-K partial 1

// ---------------------------------------------------------------------------
// helpers
// ---------------------------------------------------------------------------
__device__ __forceinline__ uint32_t smem_u32(const void* p) {
    uint32_t a;
    asm("{ .reg .u64 t; cvta.to.shared.u64 t, %1; cvt.u32.u64 %0, t; }"
        : "=r"(a) : "l"(p));
    return a;
}

#define LDSM_X4(r0, r1, r2, r3, a)                                            \
    asm volatile("ldmatrix.sync.aligned.m8n8.x4.shared.b16 {%0,%1,%2,%3}, [%4];" \
                 : "=r"(r0), "=r"(r1), "=r"(r2), "=r"(r3) : "r"(a))

__device__ __forceinline__ void mma_f16(float* c, const uint32_t* a,
                                        uint32_t b0, uint32_t b1) {
    asm volatile(
        "mma.sync.aligned.m16n8k16.row.col.f32.f16.f16.f32 "
        "{%0,%1,%2,%3}, {%4,%5,%6,%7}, {%8,%9}, {%0,%1,%2,%3};"
        : "+f"(c[0]), "+f"(c[1]), "+f"(c[2]), "+f"(c[3])
        : "r"(a[0]), "r"(a[1]), "r"(a[2]), "r"(a[3]), "r"(b0), "r"(b1));
}

#define CP_ASYNC_CG(dst, src, sz)                                             \
    asm volatile("cp.async.cg.shared.global [%0], [%1], 16, %2;"              \
                 :: "r"(dst), "l"(src), "r"(sz) : "memory")
#define CP_COMMIT() asm volatile("cp.async.commit_group;" ::: "memory")
#define CP_WAIT1()  asm volatile("cp.async.wait_group 1;" ::: "memory")

// ---------------------------------------------------------------------------
// fp16 MMA GEMM:  C = A[M,K] @ B[N,K]^T (+ bias[N] if bias != nullptr)
//   TRANSC=false: C[M,N] row-major    TRANSC=true: C^T[N,M] (coalesced rows)
//   Split-K: if kSplit > 0, blockIdx.z in {0,1} selects K-range
//            [0,kSplit) -> C0, [kSplit,K) -> C1.
// CTA tile 128x128, BK=32, 256 threads (8 warps, 2(m) x 4(n), 64x32 warp tile)
// 3-stage cp.async pipeline, one __syncthreads per iter.
// SMEM row stride 80 B => conflict-free ldmatrix.
// ---------------------------------------------------------------------------
#define BSTRIDE 80                       // bytes per row (32 halves + pad)
#define TILE_B  (128 * BSTRIDE)          // 10240 B per matrix tile
#define OFF_A   0
#define OFF_B   (TILE_B)
#define STAGE_B (2 * TILE_B)             // 20480 B per stage
#define NSTAGE  3                        // 61440 B total stages
#define SMEM_TOTAL 67584                 // epilogue 128*132*4 dominates

template <bool TRANSC>
__global__ __launch_bounds__(256, 2)
void f16_gemm(const __half* __restrict__ A, const __half* __restrict__ B,
              const float* __restrict__ bias, float* __restrict__ C0,
              float* __restrict__ C1, int M, int N, int Ktot, int kSplit)
{
    extern __shared__ char smem[];
    const uint32_t sbase = smem_u32(smem);

    const int tid  = threadIdx.x;
    const int wid  = tid >> 5;
    const int lane = tid & 31;
    const int warp_m = (wid & 1) * 64;
    const int warp_n = (wid >> 1) * 32;

    const int bm = blockIdx.y * 128;
    const int bn = blockIdx.x * 128;

    // split-K selection
    const int z    = (kSplit > 0) ? (int)blockIdx.z : 0;
    const int kOff = z ? kSplit : 0;
    const int K    = (kSplit > 0) ? (z ? (Ktot - kSplit) : kSplit) : Ktot;
    float* C = z ? C1 : C0;
    const int lda = Ktot;                 // row stride of A and B in elements

    const int nIter = (K + 31) / 32;

    // per-thread chunk coords (16B chunks): 512 chunks / 256 thr = 2 each
    const int ch0row = tid >> 2;              // rows 0..63
    const int ch0c   = tid & 3;
    const int ch1row = ch0row + 64;           // rows 64..127

    auto issue = [&](int it) {
        const int k0 = it * 32;
        const uint32_t stg = sbase + (uint32_t)(it % NSTAGE) * STAGE_B;
        const int kpos = k0 + ch0c * 8;
        const int rem = K - kpos;
        const uint32_t bytes = rem >= 8 ? 16u : (rem > 0 ? (uint32_t)(rem * 2) : 0u);
        const int ksafe = ((kpos < K) ? kpos : 0) + kOff;
#pragma unroll
        for (int j = 0; j < 2; j++) {
            int row = j ? ch1row : ch0row;
            uint32_t doff = (uint32_t)(row * BSTRIDE + ch0c * 16);
            const __half* asrc = A + (long long)(bm + row) * lda + ksafe;
            CP_ASYNC_CG(stg + OFF_A + doff, asrc, bytes);

            int ng = bn + row;
            int srow = (ng < N) ? ng : (N - 1);
            uint32_t bbytes = (ng < N) ? bytes : 0u;
            const __half* bsrc = B + (long long)srow * lda + ksafe;
            CP_ASYNC_CG(stg + OFF_B + doff, bsrc, bbytes);
        }
        CP_COMMIT();
    };

    float acc[4][4][4];
#pragma unroll
    for (int i = 0; i < 4; i++)
#pragma unroll
        for (int j = 0; j < 4; j++)
#pragma unroll
            for (int e = 0; e < 4; e++) acc[i][j][e] = 0.0f;

    issue(0);
    issue(1);
    CP_WAIT1();                 // stage 0 ready
    __syncthreads();

    const int rowSel = lane & 15;
    const uint32_t kHalf = ((uint32_t)(lane >> 4)) << 4;   // 0 or 16 B

    for (int it = 0; it < nIter; it++) {
        const uint32_t stg = sbase + (uint32_t)(it % NSTAGE) * STAGE_B;

#pragma unroll
        for (int ks = 0; ks < 2; ks++) {
            const uint32_t kb = (uint32_t)(ks * 32) + kHalf;
            uint32_t ah[4][4], bh[2][4];
#pragma unroll
            for (int mt = 0; mt < 4; mt++) {
                uint32_t ra = (uint32_t)((warp_m + mt * 16 + rowSel) * BSTRIDE) + kb;
                LDSM_X4(ah[mt][0], ah[mt][1], ah[mt][2], ah[mt][3], stg + OFF_A + ra);
            }
#pragma unroll
            for (int ng = 0; ng < 2; ng++) {
                uint32_t rb = (uint32_t)((warp_n + ng * 16 + rowSel) * BSTRIDE) + kb;
                LDSM_X4(bh[ng][0], bh[ng][1], bh[ng][2], bh[ng][3], stg + OFF_B + rb);
            }
#pragma unroll
            for (int mt = 0; mt < 4; mt++)
#pragma unroll
                for (int ng = 0; ng < 2; ng++)
#pragma unroll
                    for (int hf = 0; hf < 2; hf++)
                        mma_f16(acc[mt][ng * 2 + hf], ah[mt],
                                bh[ng][hf], bh[ng][hf + 2]);
        }

        // prefetch stage it+2 (overwrites stage (it-1)%3 — safe post-sync)
        if (it + 2 < nIter) issue(it + 2);
        else                CP_COMMIT();
        CP_WAIT1();            // stage it+1 ready
        __syncthreads();
    }

    // ---- epilogue through smem ----
    float* sf = (float*)smem;                 // 128 x 132 floats = 67584 B
    {
        const int r0 = lane >> 2;
        const int c0 = (lane & 3) * 2;
#pragma unroll
        for (int mt = 0; mt < 4; mt++)
#pragma unroll
            for (int n8 = 0; n8 < 4; n8++) {
                int row = warp_m + mt * 16 + r0;
                int col = warp_n + n8 * 8 + c0;
                float* c = acc[mt][n8];
                if (TRANSC) {
                    // stage transposed: sf[col][row], scalar stores
                    sf[col * 132 + row]           = c[0];
                    sf[(col + 1) * 132 + row]     = c[1];
                    sf[col * 132 + row + 8]       = c[2];
                    sf[(col + 1) * 132 + row + 8] = c[3];
                } else {
                    *(float2*)&sf[row * 132 + col]       = make_float2(c[0], c[1]);
                    *(float2*)&sf[(row + 8) * 132 + col] = make_float2(c[2], c[3]);
                }
            }
    }
    __syncthreads();

    if (TRANSC) {
        // C^T[N][M]: float4 along tokens; 132 ≡ 0 (mod 4) so sf reads aligned
#pragma unroll
        for (int t = 0; t < 16; t++) {
            int idx = tid + t * 256;       // 0..4095
            int col = idx >> 5;            // output channel 0..127
            int r4  = (idx & 31) * 4;      // token row group 0..124
            if (bn + col < N) {
                float b = bias ? bias[bn + col] : 0.0f;
                float4 v = *(const float4*)&sf[col * 132 + r4];
                v.x += b; v.y += b; v.z += b; v.w += b;
                *(float4*)(C + (long long)(bn + col) * M + bm + r4) = v;
            }
        }
    } else if (bn + 128 <= N) {
#pragma unroll
        for (int t = 0; t < 16; t++) {
            int idx = tid + t * 256;
            int row = idx >> 5;
            int c4 = (idx & 31) * 4;
            float4 bv = bias ? *(const float4*)(bias + bn + c4)
                             : make_float4(0.f, 0.f, 0.f, 0.f);
            float4 o;
            o.x = sf[row * 132 + c4 + 0] + bv.x;
            o.y = sf[row * 132 + c4 + 1] + bv.y;
            o.z = sf[row * 132 + c4 + 2] + bv.z;
            o.w = sf[row * 132 + c4 + 3] + bv.w;
            *(float4*)(C + (long long)(bm + row) * N + bn + c4) = o;
        }
    } else {
        for (int idx = tid; idx < 128 * 128; idx += 256) {
            int row = idx >> 7;
            int col = idx & 127;
            if (bn + col < N)
                C[(long long)(bm + row) * N + bn + col] =
                    sf[row * 132 + col] + (bias ? bias[bn + col] : 0.0f);
        }
    }
}

// ---------------------------------------------------------------------------
// split-K fixup: out = p0 + p1 + bias  (float4; N = DIM columns)
// ---------------------------------------------------------------------------
__global__ void splitk_fix_kernel(const float* __restrict__ p0,
                                  const float* __restrict__ p1,
                                  const float* __restrict__ bias,
                                  float* __restrict__ out, int n4) {
    int i = blockIdx.x * blockDim.x + threadIdx.x;
    if (i >= n4) return;
    float4 a = ((const float4*)p0)[i];
    float4 b = ((const float4*)p1)[i];
    int c4 = (i % (DIM / 4)) * 4;
    float4 bv = *(const float4*)(bias + c4);
    float4 o;
    o.x = a.x + b.x + bv.x;
    o.y = a.y + b.y + bv.y;
    o.z = a.z + b.z + bv.z;
    o.w = a.w + b.w + bv.w;
    ((float4*)out)[i] = o;
}

// ---------------------------------------------------------------------------
// Transpose + fp16 convert: in[R][C] fp32 -> out[C][R] fp16
// ---------------------------------------------------------------------------
__global__ void transpose_cvt_kernel(const float* __restrict__ in,
                                     __half* __restrict__ out, int R, int C) {
    __shared__ float t[32][33];
    int bx = blockIdx.x * 32, by = blockIdx.y * 32;
    int x = bx + threadIdx.x;
#pragma unroll
    for (int j = threadIdx.y; j < 32; j += 8) {
        int r = by + j;
        t[j][threadIdx.x] = (r < R && x < C) ? in[(long long)r * C + x] : 0.0f;
    }
    __syncthreads();
    int xo = by + threadIdx.x;
#pragma unroll
    for (int j = threadIdx.y; j < 32; j += 8) {
        int co = bx + j;
        if (co < C && xo < R)
            out[(long long)co * R + xo] = __float2half_rn(t[threadIdx.x][j]);
    }
}

// ---------------------------------------------------------------------------
// fp32 -> fp16 convert (float4 granularity)
// ---------------------------------------------------------------------------
__global__ void cvt_f16_kernel(const float* __restrict__ in,
                               __half* __restrict__ out, int n4) {
    int i = blockIdx.x * blockDim.x + threadIdx.x;
    if (i >= n4) return;
    float4 v = ((const float4*)in)[i];
    ((__half2*)out)[i * 2]     = __floats2half2_rn(v.x, v.y);
    ((__half2*)out)[i * 2 + 1] = __floats2half2_rn(v.z, v.w);
}

// ---------------------------------------------------------------------------
// Fold (gather, no atomics), reading h^T[ch][tok]: warp lanes (consecutive pc)
// hit consecutive tokens -> coalesced sectors.
// ---------------------------------------------------------------------------
__global__ void fold_kernel() {
    int idx = blockIdx.x * blockDim.x + threadIdx.x;
    const int total = NB2 * NCCH * PH * PW;
    if (idx >= total) return;

    int pc = idx % PW;
    int t = idx / PW;
    int pr = t % PH; t /= PH;
    int cch = t % NCCH;
    int b2 = t / NCCH;

    float s = 0.0f;
    int ki0 = pr % 3, kj0 = pc % 3;
#pragma unroll
    for (int ki = ki0; ki < KK; ki += 3) {
        int lh3 = pr - ki;
        if (lh3 < 0 || lh3 > 3 * (LH - 1)) continue;
        int lh = lh3 / 3;
#pragma unroll
        for (int kj = kj0; kj < KK; kj += 3) {
            int lw3 = pc - kj;
            if (lw3 < 0 || lw3 > 3 * (LW - 1)) continue;
            int lw = lw3 / 3;
            int ch = (cch * KK + ki) * KK + kj;
            int tok = (b2 * LH + lh) * LW + lw;
            s += g_ht[(long long)ch * MROWS + tok];
        }
    }
    g_F[idx] = s;
}

__device__ __forceinline__ float inv_count(int p, int lmax3) {
    int c = 0;
#pragma unroll
    for (int k = p % 3; k < KK; k += 3) {
        int l3 = p - k;
        if (l3 >= 0 && l3 <= lmax3) c++;
    }
    return 1.0f / (float)c;
}

// ---------------------------------------------------------------------------
// Unfold + normalize + ReLU -> fp16 A (4 channels / thread)
// ---------------------------------------------------------------------------
__global__ void unfold_relu_kernel() {
    int idx = blockIdx.x * blockDim.x + threadIdx.x;
    const int total = MROWS * (HD / 4);
    if (idx >= total) return;

    int c4 = (idx % (HD / 4)) * 4;
    int m = idx / (HD / 4);
    int lw = m % LW;
    int t = m / LW;
    int lh = t % LH;
    int b2 = t / LH;

    const float* Fb = g_F + (long long)b2 * NCCH * PH * PW;
    float o[4];
#pragma unroll
    for (int e = 0; e < 4; e++) {
        int ch = c4 + e;
        int kj = ch % KK;
        int t2 = ch / KK;
        int ki = t2 % KK;
        int cch = t2 / KK;
        int pr = ki + 3 * lh;
        int pc = kj + 3 * lw;
        float v = 0.0f;
        if (pr >= PP && pr < PP + HH && pc >= PP && pc < PP + WW) {
            float f = Fb[((long long)cch * PH + pr) * PW + pc];
            f = fmaxf(f, 0.0f);
            v = f * inv_count(pr, 3 * (LH - 1)) * inv_count(pc, 3 * (LW - 1));
        }
        o[e] = v;
    }
    __half2 p0 = __floats2half2_rn(o[0], o[1]);
    __half2 p1 = __floats2half2_rn(o[2], o[3]);
    __half2* dst = (__half2*)(g_Ah + (long long)m * HD + c4);
    dst[0] = p0;
    dst[1] = p1;
}

// ---------------------------------------------------------------------------
extern "C" void kernel_launch(void* const* d_in, const int* in_sizes, int n_in,
                              void* d_out, int out_size) {
    const float* x  = (const float*)d_in[0];
    const float* W1 = (const float*)d_in[1];
    const float* b1 = (const float*)d_in[2];
    const float* W2 = (const float*)d_in[3];
    const float* b2 = (const float*)d_in[4];
    float* out = (float*)d_out;

    float *htP, *P0, *P1;
    __half *xhP, *AhP, *W1hP, *W2hP;
    cudaGetSymbolAddress((void**)&htP, g_ht);
    cudaGetSymbolAddress((void**)&P0, g_P0);
    cudaGetSymbolAddress((void**)&P1, g_P1);
    cudaGetSymbolAddress((void**)&xhP, g_xh);
    cudaGetSymbolAddress((void**)&AhP, g_Ah);
    cudaGetSymbolAddress((void**)&W1hP, g_W1h);
    cudaGetSymbolAddress((void**)&W2hP, g_W2h);

    cudaFuncSetAttribute(f16_gemm<true>,
                         cudaFuncAttributeMaxDynamicSharedMemorySize, SMEM_TOTAL);
    cudaFuncSetAttribute(f16_gemm<false>,
                         cudaFuncAttributeMaxDynamicSharedMemorySize, SMEM_TOTAL);

    // Pre-transpose + convert weights to fp16, [N][K] K-major
    {
        dim3 blk(32, 8);
        dim3 g1((HD + 31) / 32, (DIM + 31) / 32);
        transpose_cvt_kernel<<<g1, blk>>>(W1, W1hP, DIM, HD);
        dim3 g2((DIM + 31) / 32, (HD + 31) / 32);
        transpose_cvt_kernel<<<g2, blk>>>(W2, W2hP, HD, DIM);
    }

    // x -> fp16
    {
        int n4 = MROWS * DIM / 4;
        cvt_f16_kernel<<<(n4 + 255) / 256, 256>>>(x, xhP, n4);
    }

    // GEMM1: h^T = (x @ W1 + b1)^T   (M=11520, N=1960, K=512), transposed out
    {
        dim3 grid((HD + 127) / 128, MROWS / 128, 1);
        f16_gemm<true><<<grid, 256, SMEM_TOTAL>>>(xhP, W1hP, b1, htP, htP,
                                                  MROWS, HD, DIM, 0);
    }

    // Fold
    {
        int total = NB2 * NCCH * PH * PW;
        fold_kernel<<<(total + 255) / 256, 256>>>();
    }

    // Unfold + normalize + ReLU -> fp16
    {
        int total = MROWS * (HD / 4);
        unfold_relu_kernel<<<(total + 255) / 256, 256>>>();
    }

    // GEMM2 (split-K=2): partials = A @ W2 over K-halves (M=11520, N=512)
    {
        dim3 grid((DIM + 127) / 128, MROWS / 128, 2);
        f16_gemm<false><<<grid, 256, SMEM_TOTAL>>>(AhP, W2hP, nullptr, P0, P1,
                                                   MROWS, DIM, HD, KSPLIT);
    }

    // fixup: out = P0 + P1 + b2
    {
        int n4 = MROWS * DIM / 4;
        splitk_fix_kernel<<<(n4 + 255) / 256, 256>>>(P0, P1, b2, out, n4);
    }
}